// round 17
// baseline (speedup 1.0000x reference)
#include <cuda_runtime.h>
#include <stdint.h>

// MaskPyramids single-pass, single-launch. 256-bit stores (st.global.v8.f32)
// on 128B-line-aligned regions, block/warp-uniform zero fast paths, and 4 v8
// iterations per thread (block = 8192 floats) to halve per-block prologue
// cost and double store ILP.
//
// grid = (7, 512): bx 0-4 -> level 200x200 (5 x 8192 >= 40000), bx 5-6 ->
// level 100x100 (2 x 8192 >= 10000); bx 6 (mostly idle) also runs the
// 50/25/13 scalar tail levels. Head h = (-start) mod 32 and tail
// (NELEM-h)&7 elems handled scalar by chunk-0 spare threads (verified
// R12-R16 scheme).
//
// Rounding replicates XLA's div->reciprocal-mul rewrite (verified exact R3):
//   rint( fl( fl(p * fl(1/200)) * H ) ), all f32 RN-even.

#define N_INST   512
#define G        28
#define CTRK     13
#define PER_INST 53294   // 40000 + 10000 + 2500 + 625 + 169

__device__ __forceinline__ float mval(const float* __restrict__ mask,
                                      int si, int sj) {
    return ((unsigned)si < (unsigned)G && (unsigned)sj < (unsigned)G)
               ? __ldg(&mask[si * G + sj]) : 0.0f;
}

__device__ __forceinline__ void stg256(float* p, const float* v) {
    asm volatile("st.global.v8.f32 [%0], {%1,%2,%3,%4,%5,%6,%7,%8};"
                 :: "l"(p), "f"(v[0]), "f"(v[1]), "f"(v[2]), "f"(v[3]),
                    "f"(v[4]), "f"(v[5]), "f"(v[6]), "f"(v[7])
                 : "memory");
}

__device__ __forceinline__ void stg256_zero(float* p) {
    float z[8] = {0.f, 0.f, 0.f, 0.f, 0.f, 0.f, 0.f, 0.f};
    stg256(p, z);
}

template<int H>
__device__ __forceinline__ void do_level(int chunk, int c0, int b0, int h,
                                         const float* __restrict__ mask,
                                         float* __restrict__ outlevel) {
    constexpr int NELEM = H * H;
    const int NB  = (NELEM - h) >> 3;          // aligned-body f8 count
    const int tid = threadIdx.x;

    // ---- block-uniform window-band test (block covers 8192 floats) ----
    const int S0  = h + chunk * 8192;          // block's first float offset
    const int S1  = S0 + 8191;
    const int rA0 = S0 / H;                    // compile-time magic div
    const int rB0 = S1 / H;
    const bool blk_hit = (rB0 + c0 >= 0) && (rA0 + c0 <= G - 1);

    if (!blk_hit) {
        // pure zero path: no window math at all
        #pragma unroll
        for (int k = 0; k < 4; k++) {
            const int f8 = chunk * 1024 + k * 256 + tid;
            if (f8 < NB) stg256_zero(outlevel + h + f8 * 8);
        }
    } else {
        const int lane0 = tid & ~31;
        #pragma unroll
        for (int k = 0; k < 4; k++) {
            const int f8 = chunk * 1024 + k * 256 + tid;
            if (f8 >= NB) break;

            // warp-uniform test (256 floats per warp)
            const int S  = h + (chunk * 1024 + k * 256 + lane0) * 8;
            const int rA = S / H;
            const int rB = (S + 255) / H;
            const bool warp_hit = (rB + c0 >= 0) && (rA + c0 <= G - 1);

            const int off = h + f8 * 8;
            float v[8];
            #pragma unroll
            for (int e = 0; e < 8; e++) v[e] = 0.0f;

            if (warp_hit) {
                const int row = off / H;
                const int col = off - row * H;
                const int si  = row + c0;
                if (col <= H - 8) {            // no row straddle (common)
                    const int sj = col - b0;
                    if ((unsigned)si < (unsigned)G && sj > -8 && sj < G) {
                        const float* mrow = mask + si * G;
                        #pragma unroll
                        for (int e = 0; e < 8; e++) {
                            const int s = sj + e;
                            if ((unsigned)s < (unsigned)G) v[e] = __ldg(&mrow[s]);
                        }
                    }
                } else {                       // straddle (rare)
                    #pragma unroll
                    for (int e = 0; e < 8; e++) {
                        int cc = col + e, r = si;
                        if (cc >= H) { cc -= H; r += 1; }
                        v[e] = mval(mask, r, cc - b0);
                    }
                }
            }
            stg256(outlevel + off, v);
        }
    }

    if (chunk == 0) {
        // head: elements [0, h), all in row 0
        if (tid < h)
            outlevel[tid] = mval(mask, c0, tid - b0);
        // tail: t = (NELEM - h) & 7 elements at the very end, row H-1
        const int t = (NELEM - h) & 7;
        const int j = tid - 64;
        if (j >= 0 && j < t)
            outlevel[NELEM - t + j] = mval(mask, H - 1 + c0, H - t + j - b0);
    }
}

template<int H, int BASE, int N>
__device__ __forceinline__ void do_tail_level(float pp0, float pp1,
                                              const float* __restrict__ mask,
                                              float* __restrict__ outrow) {
    const int lh = (int)rintf(__fmul_rn(pp0, (float)H));
    const int lw = (int)rintf(__fmul_rn(pp1, (float)H));
    const int c0 = CTRK - lh;
    const int b0 = lw - CTRK;
    for (int idx = threadIdx.x; idx < N; idx += 256) {
        const int row = idx / H;               // compile-time magic div
        const int col = idx - row * H;
        outrow[BASE + idx] = mval(mask, row + c0, col - b0);
    }
}

__global__ void __launch_bounds__(256)
fused_kernel(const int* __restrict__ pos,
             const float* __restrict__ mask,
             float* __restrict__ out) {
    const int inst = blockIdx.y;
    const int bx   = blockIdx.x;

    const float recip = 0.005f;  // fl(1/200) bit-exactly
    const float pp0 = __fmul_rn((float)__ldg(&pos[2 * inst + 0]), recip);
    const float pp1 = __fmul_rn((float)__ldg(&pos[2 * inst + 1]), recip);

    float* outrow = out + inst * PER_INST;
    // head to first 128B line; level bases (0, 40000) both 0 mod 32 floats,
    // so the same h serves both big levels. h is even (53294 % 32 = 14).
    const int h = (32 - ((inst * PER_INST) & 31)) & 31;

    if (bx < 5) {
        const int c0 = CTRK - (int)rintf(__fmul_rn(pp0, 200.f));
        const int b0 = (int)rintf(__fmul_rn(pp1, 200.f)) - CTRK;
        do_level<200>(bx, c0, b0, h, mask, outrow);
    } else {
        const int c0 = CTRK - (int)rintf(__fmul_rn(pp0, 100.f));
        const int b0 = (int)rintf(__fmul_rn(pp1, 100.f)) - CTRK;
        do_level<100>(bx - 5, c0, b0, h, mask, outrow + 40000);
        if (bx == 6) {
            do_tail_level<50, 50000, 2500>(pp0, pp1, mask, outrow);
            do_tail_level<25, 52500, 625>(pp0, pp1, mask, outrow);
            do_tail_level<13, 53125, 169>(pp0, pp1, mask, outrow);
        }
    }
}

extern "C" void kernel_launch(void* const* d_in, const int* in_sizes, int n_in,
                              void* d_out, int out_size) {
    const int*   pos  = (const int*)d_in[0];      // int32 [512, 2]
    const float* mask = (const float*)d_in[1];    // float32 [28, 28]
    float*       out  = (float*)d_out;            // float32 [512, 53294]

    fused_kernel<<<dim3(7, N_INST), 256>>>(pos, mask, out);
}